// round 4
// baseline (speedup 1.0000x reference)
#include <cuda_runtime.h>
#include <math.h>

// Problem constants
#define BATCH   2048
#define DIM     3072
#define NCLS    10
#define MDIM    9
#define TPB     256
#define GRID    148
#define PER_V4  3           // DIM / (4*TPB)
#define SCALE   0.999999f   // 1 - c*ns, c=10, ns=1e-7
#define NSTAB   1e-7f
#define EPS2    0.01f       // EPSILON^2

__device__ float g_G[NCLS * NCLS];   // W^T W, [10,10]
__device__ float g_norm[BATCH];      // per-sample Frobenius norms

// ---------------------------------------------------------------------------
// Kernel 1: G = W^T W.  One block per (l1,l2) entry.
// ---------------------------------------------------------------------------
__global__ void k_gram(const float* __restrict__ W) {
    const int l1 = blockIdx.x / NCLS;
    const int l2 = blockIdx.x % NCLS;
    float a = 0.f;
    for (int d = threadIdx.x; d < DIM; d += TPB)
        a += W[d * NCLS + l1] * W[d * NCLS + l2];
    #pragma unroll
    for (int off = 16; off; off >>= 1)
        a += __shfl_xor_sync(0xFFFFFFFFu, a, off);
    __shared__ float sh[TPB / 32];
    const int w = threadIdx.x >> 5;
    if ((threadIdx.x & 31) == 0) sh[w] = a;
    __syncthreads();
    if (threadIdx.x == 0) {
        float t = 0.f;
        #pragma unroll
        for (int i = 0; i < TPB / 32; i++) t += sh[i];
        g_G[blockIdx.x] = t;
    }
}

// ---------------------------------------------------------------------------
// Kernel 2: persistent blocks; W in registers; 2 samples per iteration.
// Per sample: logits = x@W + b  ->  softmax  ->  rank-structured
// gram = A G A^T  ->  ||gram - factor*I||_F  -> g_norm[s].
// ---------------------------------------------------------------------------
__global__ void __launch_bounds__(TPB, 1)
k_main(const float* __restrict__ data,
       const float* __restrict__ W,
       const float* __restrict__ b) {
    __shared__ float Gs[NCLS * NCLS];
    __shared__ float part[2][TPB / 32][NCLS];
    __shared__ float shp[2][NCLS];
    __shared__ float sha[2][MDIM];
    __shared__ float shb[2][MDIM];
    __shared__ float shg[2][NCLS];

    const int tid  = threadIdx.x;
    const int lane = tid & 31;
    const int wid  = tid >> 5;

    if (tid < NCLS * NCLS) Gs[tid] = g_G[tid];

    // Load this thread's W rows into registers.  Thread handles dims
    // d = 4*(tid + k*TPB) + c  for k in [0,3), c in [0,4).
    float wreg[PER_V4][4][NCLS];
    #pragma unroll
    for (int k = 0; k < PER_V4; k++) {
        #pragma unroll
        for (int c = 0; c < 4; c++) {
            const int d = 4 * (tid + k * TPB) + c;
            #pragma unroll
            for (int l = 0; l < NCLS; l++)
                wreg[k][c][l] = W[d * NCLS + l];
        }
    }
    __syncthreads();

    for (int base = 2 * blockIdx.x; base < BATCH; base += 2 * gridDim.x) {
        // ---- load x for both samples as float4 (LDG.128, coalesced)
        float4 xv[2][PER_V4];
        #pragma unroll
        for (int ss = 0; ss < 2; ss++) {
            const float4* x4 =
                (const float4*)(data + (size_t)(base + ss) * DIM);
            #pragma unroll
            for (int k = 0; k < PER_V4; k++)
                xv[ss][k] = x4[tid + k * TPB];
        }
        float acc0[NCLS], acc1[NCLS];
        #pragma unroll
        for (int l = 0; l < NCLS; l++) { acc0[l] = 0.f; acc1[l] = 0.f; }
        #pragma unroll
        for (int k = 0; k < PER_V4; k++) {
            const float x0a = xv[0][k].x, x0b = xv[0][k].y,
                        x0c = xv[0][k].z, x0d = xv[0][k].w;
            const float x1a = xv[1][k].x, x1b = xv[1][k].y,
                        x1c = xv[1][k].z, x1d = xv[1][k].w;
            #pragma unroll
            for (int l = 0; l < NCLS; l++) {
                acc0[l] += x0a * wreg[k][0][l] + x0b * wreg[k][1][l]
                         + x0c * wreg[k][2][l] + x0d * wreg[k][3][l];
                acc1[l] += x1a * wreg[k][0][l] + x1b * wreg[k][1][l]
                         + x1c * wreg[k][2][l] + x1d * wreg[k][3][l];
            }
        }
        // ---- warp-level reduce of the 20 partials
        #pragma unroll
        for (int l = 0; l < NCLS; l++) {
            #pragma unroll
            for (int off = 16; off; off >>= 1) {
                acc0[l] += __shfl_xor_sync(0xFFFFFFFFu, acc0[l], off);
                acc1[l] += __shfl_xor_sync(0xFFFFFFFFu, acc1[l], off);
            }
        }
        if (lane == 0) {
            #pragma unroll
            for (int l = 0; l < NCLS; l++) {
                part[0][wid][l] = acc0[l];
                part[1][wid][l] = acc1[l];
            }
        }
        __syncthreads();

        // ---- epilogue: warp 0 handles sample base, warp 1 handles base+1
        if (wid < 2) {
            const int w = wid;
            float logit = -1e30f;
            if (lane < NCLS) {
                float v = b[lane];
                #pragma unroll
                for (int ww = 0; ww < TPB / 32; ww++) v += part[w][ww][lane];
                logit = v;
            }
            // softmax across lanes 0..9 (16-lane butterfly; lanes 10..15
            // neutral; lanes 16..31 produce garbage here and get the
            // correct scalar values via broadcast below).
            float mval = logit;
            #pragma unroll
            for (int off = 8; off; off >>= 1)
                mval = fmaxf(mval, __shfl_xor_sync(0xFFFFFFFFu, mval, off));
            float e = (lane < NCLS) ? expf(logit - mval) : 0.f;
            float ssum = e;
            #pragma unroll
            for (int off = 8; off; off >>= 1)
                ssum += __shfl_xor_sync(0xFFFFFFFFu, ssum, off);
            const float p  = e / ssum;
            const float q  = p * SCALE + NSTAB;
            const float nc = sqrtf(q);
            float ncs = (lane < NCLS) ? nc : 0.f;
            #pragma unroll
            for (int off = 8; off; off >>= 1)
                ncs += __shfl_xor_sync(0xFFFFFFFFu, ncs, off);
            const float nc9 = __shfl_sync(0xFFFFFFFFu, nc, 9);
            const float p9  = __shfl_sync(0xFFFFFFFFu, p, 9);
            const float denom = 1.f - nc9;
            float arg = ncs * 0.3162277660168379f;   // 1/sqrt(10)
            arg = fminf(arg, 1.f);
            const float delta  = 2.f * acosf(arg);
            float factor = delta * delta / (4.f * denom * denom * EPS2);
            // BUGFIX R2: lanes 16..31 reduced over an all-zero half-warp and
            // would compute delta = pi.  Broadcast the correct factor from
            // lane 0 so all 32 lanes (which all evaluate gram entries below)
            // subtract the right diagonal term.
            factor = __shfl_sync(0xFFFFFFFFu, factor, 0);

            if (lane < NCLS) shp[w][lane] = p;
            if (lane < MDIM) {
                // alpha_i = scale * p_i / (nc_i * denom)
                // beta_i  = scale * nc_i * p_9 / (nc_9 * denom^2)
                sha[w][lane] = SCALE * p / (nc * denom);
                shb[w][lane] = SCALE * nc * p9 / (nc9 * denom * denom);
            }
            __syncwarp();
            if (lane < NCLS) {
                float gg = 0.f;
                #pragma unroll
                for (int k2 = 0; k2 < NCLS; k2++)
                    gg += Gs[lane * NCLS + k2] * shp[w][k2];
                shg[w][lane] = gg;
            }
            __syncwarp();
            float sdot = 0.f;
            #pragma unroll
            for (int k2 = 0; k2 < NCLS; k2++)
                sdot += shp[w][k2] * shg[w][k2];
            const float tval = shg[w][MDIM];
            const float r    = Gs[MDIM * NCLS + MDIM];

            // M = A G A^T via rank structure: A = diag(alpha)|0 + beta e9^T + gamma p^T,
            // gamma = -(alpha+beta).  81 entries over 32 lanes (3 reps).
            float ssq = 0.f;
            #pragma unroll
            for (int rep = 0; rep < 3; rep++) {
                const int e2 = lane + rep * 32;
                if (e2 < MDIM * MDIM) {
                    const int i = e2 / MDIM, j = e2 % MDIM;
                    const float ai = sha[w][i], aj = sha[w][j];
                    const float bi = shb[w][i], bj = shb[w][j];
                    const float gi = -(ai + bi), gj = -(aj + bj);
                    const float ggi = shg[w][i], ggj = shg[w][j];
                    float Mij = ai * aj * Gs[i * NCLS + j]
                              + ai * bj * Gs[i * NCLS + MDIM]
                              + bi * aj * Gs[j * NCLS + MDIM]
                              + ai * gj * ggi
                              + gi * aj * ggj
                              + bi * bj * r
                              + (bi * gj + gi * bj) * tval
                              + gi * gj * sdot;
                    const float v2 = Mij - ((i == j) ? factor : 0.f);
                    ssq += v2 * v2;
                }
            }
            #pragma unroll
            for (int off = 16; off; off >>= 1)
                ssq += __shfl_xor_sync(0xFFFFFFFFu, ssq, off);
            if (lane == 0) g_norm[base + w] = sqrtf(ssq);
        }
        __syncthreads();
    }
}

// ---------------------------------------------------------------------------
// Kernel 3: deterministic tree reduction of the 2048 norms.
// ---------------------------------------------------------------------------
__global__ void k_final(float* __restrict__ out) {
    __shared__ float sh[1024];
    const int t = threadIdx.x;
    sh[t] = g_norm[t] + g_norm[t + 1024];
    __syncthreads();
    #pragma unroll
    for (int off = 512; off; off >>= 1) {
        if (t < off) sh[t] += sh[t + off];
        __syncthreads();
    }
    if (t == 0) out[0] = sh[0] * (1.0f / (BATCH * 81.0f));
}

// ---------------------------------------------------------------------------
extern "C" void kernel_launch(void* const* d_in, const int* in_sizes, int n_in,
                              void* d_out, int out_size) {
    // Bind inputs by size (robust to metadata ordering):
    //   data = 2048*3*32*32 = 6291456,  W = 3072*10 = 30720,  b = 10.
    const float* data = 0;
    const float* W    = 0;
    const float* b    = 0;
    for (int i = 0; i < n_in; i++) {
        if (in_sizes[i] == BATCH * DIM)      data = (const float*)d_in[i];
        else if (in_sizes[i] == DIM * NCLS)  W    = (const float*)d_in[i];
        else if (in_sizes[i] == NCLS)        b    = (const float*)d_in[i];
    }
    float* out = (float*)d_out;              // scalar

    k_gram <<<NCLS * NCLS, TPB>>>(W);
    k_main <<<GRID, TPB>>>(data, W, b);
    k_final<<<1, 1024>>>(out);
}

// round 6
// speedup vs baseline: 1.0978x; 1.0978x over previous
#include <cuda_runtime.h>
#include <math.h>

// Problem constants
#define BATCH   2048
#define DIM     3072
#define NCLS    10
#define MDIM    9
#define TPB     256
#define NWARP   (TPB / 32)
#define GRID    148
#define PER_V4  3           // DIM / (4*TPB)
#define SCALE   0.999999f   // 1 - c*ns, c=10, ns=1e-7
#define NSTAB   1e-7f
#define EPS2    0.01f       // EPSILON^2

__device__ float        g_norm[BATCH];   // per-sample Frobenius norms
__device__ unsigned int g_count;          // zero-initialized; reset in-kernel

// ---------------------------------------------------------------------------
// Single fused kernel:
//   prologue: W -> registers; G = W^T W computed in-block (each block
//             redundantly; W is register-resident so it costs ~660 FMA/thread)
//   loop:     2 samples/iter; logits = x@W + b via register FMA + 3-step
//             warp butterfly; epilogue on warps 0/1 computes the
//             rank-structured gram = A G A^T and ||gram - factor*I||_F.
//   tail:     last block to finish reduces g_norm[2048] -> out (deterministic
//             fixed-order tree) and resets the arrival counter.
// ---------------------------------------------------------------------------
__global__ void __launch_bounds__(TPB, 1)
k_fused(const float* __restrict__ data,
        const float* __restrict__ W,
        const float* __restrict__ b,
        float* __restrict__ out) {
    __shared__ float Gs[NCLS * NCLS];
    __shared__ float shop[NWARP][56];                 // G reduction staging
    __shared__ float part[2][2][NWARP][4][NCLS];      // buf, sample, warp, grp
    __shared__ float shp[2][NCLS];
    __shared__ float sha[2][MDIM];
    __shared__ float shb[2][MDIM];
    __shared__ float shg[2][NCLS];
    __shared__ float red[TPB];
    __shared__ unsigned int s_rank;

    const int tid  = threadIdx.x;
    const int lane = tid & 31;
    const int wid  = tid >> 5;

    // ---- W rows into registers: thread handles d = 4*(tid+k*TPB)+c
    float wreg[PER_V4][4][NCLS];
    #pragma unroll
    for (int k = 0; k < PER_V4; k++) {
        #pragma unroll
        for (int c = 0; c < 4; c++) {
            const int d = 4 * (tid + k * TPB) + c;
            #pragma unroll
            for (int l = 0; l < NCLS; l++)
                wreg[k][c][l] = W[d * NCLS + l];
        }
    }

    // ---- in-block G = W^T W (upper triangle, 55 entries)
    {
        float op[55];
        #pragma unroll
        for (int e = 0; e < 55; e++) op[e] = 0.f;
        #pragma unroll
        for (int k = 0; k < PER_V4; k++) {
            #pragma unroll
            for (int c = 0; c < 4; c++) {
                int e = 0;
                #pragma unroll
                for (int i = 0; i < NCLS; i++) {
                    #pragma unroll
                    for (int j = i; j < NCLS; j++) {
                        op[e] += wreg[k][c][i] * wreg[k][c][j];
                        e++;
                    }
                }
            }
        }
        #pragma unroll
        for (int e = 0; e < 55; e++) {
            #pragma unroll
            for (int off = 16; off; off >>= 1)
                op[e] += __shfl_xor_sync(0xFFFFFFFFu, op[e], off);
        }
        if (lane == 0) {
            #pragma unroll
            for (int e = 0; e < 55; e++) shop[wid][e] = op[e];
        }
    }
    __syncthreads();
    if (tid < 55) {
        float t = 0.f;
        #pragma unroll
        for (int w = 0; w < NWARP; w++) t += shop[w][tid];
        int e = tid, i = 0;
        while (e >= NCLS - i) { e -= NCLS - i; i++; }
        const int j = i + e;
        Gs[i * NCLS + j] = t;
        Gs[j * NCLS + i] = t;
    }
    __syncthreads();

    // bias into epilogue-warp registers (one global load)
    const float breg = (wid < 2 && lane < NCLS) ? b[lane] : 0.f;

    // ---- main loop: 2 samples per iteration, ping-pong part buffer
    int buf = 0;
    for (int base = 2 * blockIdx.x; base < BATCH;
         base += 2 * gridDim.x, buf ^= 1) {
        float4 xv[2][PER_V4];
        #pragma unroll
        for (int ss = 0; ss < 2; ss++) {
            const float4* x4 =
                (const float4*)(data + (size_t)(base + ss) * DIM);
            #pragma unroll
            for (int k = 0; k < PER_V4; k++)
                xv[ss][k] = x4[tid + k * TPB];
        }
        float acc0[NCLS], acc1[NCLS];
        #pragma unroll
        for (int l = 0; l < NCLS; l++) { acc0[l] = 0.f; acc1[l] = 0.f; }
        #pragma unroll
        for (int k = 0; k < PER_V4; k++) {
            const float x0a = xv[0][k].x, x0b = xv[0][k].y,
                        x0c = xv[0][k].z, x0d = xv[0][k].w;
            const float x1a = xv[1][k].x, x1b = xv[1][k].y,
                        x1c = xv[1][k].z, x1d = xv[1][k].w;
            #pragma unroll
            for (int l = 0; l < NCLS; l++) {
                acc0[l] += x0a * wreg[k][0][l] + x0b * wreg[k][1][l]
                         + x0c * wreg[k][2][l] + x0d * wreg[k][3][l];
                acc1[l] += x1a * wreg[k][0][l] + x1b * wreg[k][1][l]
                         + x1c * wreg[k][2][l] + x1d * wreg[k][3][l];
            }
        }
        // 3-step butterfly: leaves group sums keyed by (lane & 3)
        #pragma unroll
        for (int l = 0; l < NCLS; l++) {
            #pragma unroll
            for (int off = 16; off >= 4; off >>= 1) {
                acc0[l] += __shfl_xor_sync(0xFFFFFFFFu, acc0[l], off);
                acc1[l] += __shfl_xor_sync(0xFFFFFFFFu, acc1[l], off);
            }
        }
        if (lane < 4) {
            #pragma unroll
            for (int l = 0; l < NCLS; l++) {
                part[buf][0][wid][lane][l] = acc0[l];
                part[buf][1][wid][lane][l] = acc1[l];
            }
        }
        __syncthreads();   // single barrier per iteration (ping-pong buffer)

        // ---- epilogue: warp 0 -> sample base, warp 1 -> sample base+1
        if (wid < 2) {
            const int w = wid;
            float logit = -1e30f;
            if (lane < NCLS) {
                float v0 = breg, v1 = 0.f, v2 = 0.f, v3 = 0.f;
                #pragma unroll
                for (int ww = 0; ww < NWARP; ww++) {
                    v0 += part[buf][w][ww][0][lane];
                    v1 += part[buf][w][ww][1][lane];
                    v2 += part[buf][w][ww][2][lane];
                    v3 += part[buf][w][ww][3][lane];
                }
                logit = (v0 + v1) + (v2 + v3);
            }
            // softmax over lanes 0..9 (16-lane butterfly; lanes 16..31 get
            // correct scalars via the factor broadcast below)
            float mval = logit;
            #pragma unroll
            for (int off = 8; off; off >>= 1)
                mval = fmaxf(mval, __shfl_xor_sync(0xFFFFFFFFu, mval, off));
            float e = (lane < NCLS) ? expf(logit - mval) : 0.f;
            float ssum = e;
            #pragma unroll
            for (int off = 8; off; off >>= 1)
                ssum += __shfl_xor_sync(0xFFFFFFFFu, ssum, off);
            const float p  = e / ssum;
            const float q  = p * SCALE + NSTAB;
            const float nc = sqrtf(q);
            float ncs = (lane < NCLS) ? nc : 0.f;
            #pragma unroll
            for (int off = 8; off; off >>= 1)
                ncs += __shfl_xor_sync(0xFFFFFFFFu, ncs, off);
            const float nc9 = __shfl_sync(0xFFFFFFFFu, nc, 9);
            const float p9  = __shfl_sync(0xFFFFFFFFu, p, 9);
            const float denom = 1.f - nc9;
            float arg = ncs * 0.3162277660168379f;   // 1/sqrt(10)
            arg = fminf(arg, 1.f);
            const float delta  = 2.f * acosf(arg);
            float factor = delta * delta / (4.f * denom * denom * EPS2);
            factor = __shfl_sync(0xFFFFFFFFu, factor, 0);  // lanes 16..31 fix

            if (lane < NCLS) shp[w][lane] = p;
            if (lane < MDIM) {
                sha[w][lane] = SCALE * p / (nc * denom);
                shb[w][lane] = SCALE * nc * p9 / (nc9 * denom * denom);
            }
            __syncwarp();
            if (lane < NCLS) {
                float gg = 0.f;
                #pragma unroll
                for (int k2 = 0; k2 < NCLS; k2++)
                    gg += Gs[lane * NCLS + k2] * shp[w][k2];
                shg[w][lane] = gg;
            }
            __syncwarp();
            float sdot = 0.f;
            #pragma unroll
            for (int k2 = 0; k2 < NCLS; k2++)
                sdot += shp[w][k2] * shg[w][k2];
            const float tval = shg[w][MDIM];
            const float r    = Gs[MDIM * NCLS + MDIM];

            // M = A G A^T via rank structure (81 entries over 32 lanes)
            float ssq = 0.f;
            #pragma unroll
            for (int rep = 0; rep < 3; rep++) {
                const int e2 = lane + rep * 32;
                if (e2 < MDIM * MDIM) {
                    const int i = e2 / MDIM, j = e2 % MDIM;
                    const float ai = sha[w][i], aj = sha[w][j];
                    const float bi = shb[w][i], bj = shb[w][j];
                    const float gi = -(ai + bi), gj = -(aj + bj);
                    const float ggi = shg[w][i], ggj = shg[w][j];
                    float Mij = ai * aj * Gs[i * NCLS + j]
                              + ai * bj * Gs[i * NCLS + MDIM]
                              + bi * aj * Gs[j * NCLS + MDIM]
                              + ai * gj * ggi
                              + gi * aj * ggj
                              + bi * bj * r
                              + (bi * gj + gi * bj) * tval
                              + gi * gj * sdot;
                    const float v2 = Mij - ((i == j) ? factor : 0.f);
                    ssq += v2 * v2;
                }
            }
            #pragma unroll
            for (int off = 16; off; off >>= 1)
                ssq += __shfl_xor_sync(0xFFFFFFFFu, ssq, off);
            if (lane == 0) g_norm[base + w] = sqrtf(ssq);
        }
    }

    // ---- fused final reduction: last block to arrive does it
    __syncthreads();
    if (tid == 0) {
        __threadfence();                        // publish g_norm writes
        s_rank = atomicAdd(&g_count, 1u);
    }
    __syncthreads();
    if (s_rank == GRID - 1) {                   // uniform across block
        __threadfence();                        // acquire others' g_norm
        float t0 = 0.f, t1 = 0.f;
        #pragma unroll
        for (int k = 0; k < BATCH / TPB; k += 2) {
            t0 += g_norm[tid + k * TPB];
            t1 += g_norm[tid + (k + 1) * TPB];
        }
        red[tid] = t0 + t1;
        __syncthreads();
        #pragma unroll
        for (int off = TPB / 2; off; off >>= 1) {
            if (tid < off) red[tid] += red[tid + off];
            __syncthreads();
        }
        if (tid == 0) {
            out[0] = red[0] * (1.0f / (BATCH * 81.0f));
            g_count = 0;                        // reset for next graph replay
        }
    }
}

// ---------------------------------------------------------------------------
extern "C" void kernel_launch(void* const* d_in, const int* in_sizes, int n_in,
                              void* d_out, int out_size) {
    // Bind inputs by element count (robust to ordering):
    //   data = 6291456, W = 30720, b = 10.
    const float* data = 0;
    const float* W    = 0;
    const float* b    = 0;
    for (int i = 0; i < n_in; i++) {
        if (in_sizes[i] == BATCH * DIM)      data = (const float*)d_in[i];
        else if (in_sizes[i] == DIM * NCLS)  W    = (const float*)d_in[i];
        else if (in_sizes[i] == NCLS)        b    = (const float*)d_in[i];
    }
    float* out = (float*)d_out;

    k_fused<<<GRID, TPB>>>(data, W, b, out);
}

// round 7
// speedup vs baseline: 1.2339x; 1.1240x over previous
#include <cuda_runtime.h>
#include <math.h>

// Problem constants
#define BATCH   2048
#define DIM     3072
#define NCLS    10
#define MDIM    9
#define TPB     256
#define NWARP   (TPB / 32)
#define GRID    148
#define PER_V4  3           // DIM / (4*TPB)
#define SCALE   0.999999f   // 1 - c*ns, c=10, ns=1e-7
#define NSTAB   1e-7f
#define EPS2    0.01f       // EPSILON^2

__device__ float        g_norm[BATCH];   // per-sample Frobenius norms
__device__ unsigned int g_count;          // zero-initialized; reset in-kernel

// ---------------------------------------------------------------------------
// Fused kernel, round 7: software-pipelined x prefetch, rotating epilogue
// duty (warp pair (it&3)*2), 2-step butterfly + smem gather.
// ---------------------------------------------------------------------------
__global__ void __launch_bounds__(TPB, 1)
k_fused(const float* __restrict__ data,
        const float* __restrict__ W,
        const float* __restrict__ b,
        float* __restrict__ out) {
    __shared__ float Gs[NCLS * NCLS];
    __shared__ float shop[NWARP][56];             // G reduction staging
    __shared__ float part[2][2][NWARP][8][NCLS];  // buf, sample, warp, group
    __shared__ float shp[2][NCLS];
    __shared__ float sha[2][MDIM];
    __shared__ float shb[2][MDIM];
    __shared__ float shg[2][NCLS];
    __shared__ float red[TPB];
    __shared__ unsigned int s_rank;

    const int tid  = threadIdx.x;
    const int lane = tid & 31;
    const int wid  = tid >> 5;

    // ---- W rows into registers via vectorized loads: for each k, rows
    // d0..d0+3 (d0 = 4*(tid+k*TPB)) are 40 consecutive floats = 10 LDG.128.
    float wreg[PER_V4][4][NCLS];
    #pragma unroll
    for (int k = 0; k < PER_V4; k++) {
        const int d0 = 4 * (tid + k * TPB);
        const float4* wp = (const float4*)(W + (size_t)d0 * NCLS);
        float wf[40];
        #pragma unroll
        for (int i = 0; i < 10; i++) {
            const float4 t = wp[i];
            wf[4 * i + 0] = t.x; wf[4 * i + 1] = t.y;
            wf[4 * i + 2] = t.z; wf[4 * i + 3] = t.w;
        }
        #pragma unroll
        for (int c = 0; c < 4; c++)
            #pragma unroll
            for (int l = 0; l < NCLS; l++)
                wreg[k][c][l] = wf[c * NCLS + l];
    }

    // ---- in-block G = W^T W (upper triangle, 55 entries); one-time cost
    {
        float op[55];
        #pragma unroll
        for (int e = 0; e < 55; e++) op[e] = 0.f;
        #pragma unroll
        for (int k = 0; k < PER_V4; k++) {
            #pragma unroll
            for (int c = 0; c < 4; c++) {
                int e = 0;
                #pragma unroll
                for (int i = 0; i < NCLS; i++) {
                    #pragma unroll
                    for (int j = i; j < NCLS; j++) {
                        op[e] += wreg[k][c][i] * wreg[k][c][j];
                        e++;
                    }
                }
            }
        }
        #pragma unroll
        for (int e = 0; e < 55; e++) {
            #pragma unroll
            for (int off = 16; off; off >>= 1)
                op[e] += __shfl_xor_sync(0xFFFFFFFFu, op[e], off);
        }
        if (lane == 0) {
            #pragma unroll
            for (int e = 0; e < 55; e++) shop[wid][e] = op[e];
        }
    }
    __syncthreads();
    if (tid < 55) {
        float t = 0.f;
        #pragma unroll
        for (int w = 0; w < NWARP; w++) t += shop[w][tid];
        int e = tid, i = 0;
        while (e >= NCLS - i) { e -= NCLS - i; i++; }
        const int j = i + e;
        Gs[i * NCLS + j] = t;
        Gs[j * NCLS + i] = t;
    }
    __syncthreads();

    const float breg = (lane < NCLS) ? b[lane] : 0.f;

    // ---- software-pipelined main loop
    const int step = 2 * gridDim.x;
    float4 xv[2][PER_V4];
    {
        const int base0 = 2 * blockIdx.x;
        if (base0 < BATCH) {
            #pragma unroll
            for (int ss = 0; ss < 2; ss++) {
                const float4* x4 =
                    (const float4*)(data + (size_t)(base0 + ss) * DIM);
                #pragma unroll
                for (int k = 0; k < PER_V4; k++)
                    xv[ss][k] = x4[tid + k * TPB];
            }
        }
    }

    int buf = 0, it = 0;
    for (int base = 2 * blockIdx.x; base < BATCH;
         base += step, buf ^= 1, it++) {
        // ---- GEMV partials from prefetched xv
        float acc0[NCLS], acc1[NCLS];
        #pragma unroll
        for (int l = 0; l < NCLS; l++) { acc0[l] = 0.f; acc1[l] = 0.f; }
        #pragma unroll
        for (int k = 0; k < PER_V4; k++) {
            const float x0a = xv[0][k].x, x0b = xv[0][k].y,
                        x0c = xv[0][k].z, x0d = xv[0][k].w;
            const float x1a = xv[1][k].x, x1b = xv[1][k].y,
                        x1c = xv[1][k].z, x1d = xv[1][k].w;
            #pragma unroll
            for (int l = 0; l < NCLS; l++) {
                acc0[l] += x0a * wreg[k][0][l] + x0b * wreg[k][1][l]
                         + x0c * wreg[k][2][l] + x0d * wreg[k][3][l];
                acc1[l] += x1a * wreg[k][0][l] + x1b * wreg[k][1][l]
                         + x1c * wreg[k][2][l] + x1d * wreg[k][3][l];
            }
        }
        // 2-step butterfly: lanes sharing (lane & 7) hold the 4-lane group sum
        #pragma unroll
        for (int l = 0; l < NCLS; l++) {
            #pragma unroll
            for (int off = 16; off >= 8; off >>= 1) {
                acc0[l] += __shfl_xor_sync(0xFFFFFFFFu, acc0[l], off);
                acc1[l] += __shfl_xor_sync(0xFFFFFFFFu, acc1[l], off);
            }
        }
        if (lane < 8) {
            #pragma unroll
            for (int l = 0; l < NCLS; l++) {
                part[buf][0][wid][lane][l] = acc0[l];
                part[buf][1][wid][lane][l] = acc1[l];
            }
        }
        __syncthreads();   // single barrier per iteration

        // ---- prefetch next iteration's x (in flight through the epilogue)
        const int nbase = base + step;
        float4 nxv[2][PER_V4];
        if (nbase < BATCH) {
            #pragma unroll
            for (int ss = 0; ss < 2; ss++) {
                const float4* x4 =
                    (const float4*)(data + (size_t)(nbase + ss) * DIM);
                #pragma unroll
                for (int k = 0; k < PER_V4; k++)
                    nxv[ss][k] = x4[tid + k * TPB];
            }
        }

        // ---- epilogue on rotating warp pair: warps 2*(it&3), 2*(it&3)+1
        if ((wid >> 1) == (it & 3)) {
            const int w = wid & 1;
            float logit = -1e30f;
            if (lane < NCLS) {
                float v0 = breg, v1 = 0.f;
                #pragma unroll
                for (int ww = 0; ww < NWARP; ww++) {
                    #pragma unroll
                    for (int g = 0; g < 8; g += 2) {
                        v0 += part[buf][w][ww][g][lane];
                        v1 += part[buf][w][ww][g + 1][lane];
                    }
                }
                logit = v0 + v1;
            }
            // softmax over lanes 0..9 (16-lane butterfly; lanes 16..31 fixed
            // via the factor broadcast below)
            float mval = logit;
            #pragma unroll
            for (int off = 8; off; off >>= 1)
                mval = fmaxf(mval, __shfl_xor_sync(0xFFFFFFFFu, mval, off));
            float e = (lane < NCLS) ? expf(logit - mval) : 0.f;
            float ssum = e;
            #pragma unroll
            for (int off = 8; off; off >>= 1)
                ssum += __shfl_xor_sync(0xFFFFFFFFu, ssum, off);
            const float p  = e / ssum;
            const float q  = p * SCALE + NSTAB;
            const float nc = sqrtf(q);
            float ncs = (lane < NCLS) ? nc : 0.f;
            #pragma unroll
            for (int off = 8; off; off >>= 1)
                ncs += __shfl_xor_sync(0xFFFFFFFFu, ncs, off);
            const float nc9 = __shfl_sync(0xFFFFFFFFu, nc, 9);
            const float p9  = __shfl_sync(0xFFFFFFFFu, p, 9);
            const float denom = 1.f - nc9;
            float arg = ncs * 0.3162277660168379f;   // 1/sqrt(10)
            arg = fminf(arg, 1.f);
            const float delta  = 2.f * acosf(arg);
            float factor = delta * delta / (4.f * denom * denom * EPS2);
            factor = __shfl_sync(0xFFFFFFFFu, factor, 0);

            if (lane < NCLS) shp[w][lane] = p;
            if (lane < MDIM) {
                sha[w][lane] = SCALE * p / (nc * denom);
                shb[w][lane] = SCALE * nc * p9 / (nc9 * denom * denom);
            }
            __syncwarp();
            if (lane < NCLS) {
                float gg = 0.f;
                #pragma unroll
                for (int k2 = 0; k2 < NCLS; k2++)
                    gg += Gs[lane * NCLS + k2] * shp[w][k2];
                shg[w][lane] = gg;
            }
            __syncwarp();
            float sdot = 0.f;
            #pragma unroll
            for (int k2 = 0; k2 < NCLS; k2++)
                sdot += shp[w][k2] * shg[w][k2];
            const float tval = shg[w][MDIM];
            const float r    = Gs[MDIM * NCLS + MDIM];

            // M = A G A^T via rank structure (81 entries over 32 lanes)
            float ssq = 0.f;
            #pragma unroll
            for (int rep = 0; rep < 3; rep++) {
                const int e2 = lane + rep * 32;
                if (e2 < MDIM * MDIM) {
                    const int i = e2 / MDIM, j = e2 % MDIM;
                    const float ai = sha[w][i], aj = sha[w][j];
                    const float bi = shb[w][i], bj = shb[w][j];
                    const float gi = -(ai + bi), gj = -(aj + bj);
                    const float ggi = shg[w][i], ggj = shg[w][j];
                    float Mij = ai * aj * Gs[i * NCLS + j]
                              + ai * bj * Gs[i * NCLS + MDIM]
                              + bi * aj * Gs[j * NCLS + MDIM]
                              + ai * gj * ggi
                              + gi * aj * ggj
                              + bi * bj * r
                              + (bi * gj + gi * bj) * tval
                              + gi * gj * sdot;
                    const float v2 = Mij - ((i == j) ? factor : 0.f);
                    ssq += v2 * v2;
                }
            }
            #pragma unroll
            for (int off = 16; off; off >>= 1)
                ssq += __shfl_xor_sync(0xFFFFFFFFu, ssq, off);
            if (lane == 0) g_norm[base + w] = sqrtf(ssq);
        }

        // rotate prefetched x into place
        #pragma unroll
        for (int ss = 0; ss < 2; ss++)
            #pragma unroll
            for (int k = 0; k < PER_V4; k++)
                xv[ss][k] = nxv[ss][k];
    }

    // ---- fused final reduction: last block to arrive does it
    __syncthreads();
    if (tid == 0) {
        __threadfence();                        // publish g_norm writes
        s_rank = atomicAdd(&g_count, 1u);
    }
    __syncthreads();
    if (s_rank == GRID - 1) {                   // uniform across block
        __threadfence();                        // acquire others' g_norm
        float t0 = 0.f, t1 = 0.f;
        #pragma unroll
        for (int k = 0; k < BATCH / TPB; k += 2) {
            t0 += g_norm[tid + k * TPB];
            t1 += g_norm[tid + (k + 1) * TPB];
        }
        red[tid] = t0 + t1;
        __syncthreads();
        #pragma unroll
        for (int off = TPB / 2; off; off >>= 1) {
            if (tid < off) red[tid] += red[tid + off];
            __syncthreads();
        }
        if (tid == 0) {
            out[0] = red[0] * (1.0f / (BATCH * 81.0f));
            g_count = 0;                        // reset for next graph replay
        }
    }
}

// ---------------------------------------------------------------------------
extern "C" void kernel_launch(void* const* d_in, const int* in_sizes, int n_in,
                              void* d_out, int out_size) {
    // Bind inputs by element count (robust to ordering):
    //   data = 6291456, W = 30720, b = 10.
    const float* data = 0;
    const float* W    = 0;
    const float* b    = 0;
    for (int i = 0; i < n_in; i++) {
        if (in_sizes[i] == BATCH * DIM)      data = (const float*)d_in[i];
        else if (in_sizes[i] == DIM * NCLS)  W    = (const float*)d_in[i];
        else if (in_sizes[i] == NCLS)        b    = (const float*)d_in[i];
    }
    float* out = (float*)d_out;

    k_fused<<<GRID, TPB>>>(data, W, b, out);
}

// round 8
// speedup vs baseline: 1.7381x; 1.4086x over previous
#include <cuda_runtime.h>
#include <math.h>

// Problem constants
#define BATCH 2048
#define DIM   3072
#define NCLS  10
#define MDIM  9
#define TPB   256
#define NWARP 8
#define GRID  148
#define NTASK (BATCH / 2)      // 1024 tasks, 2 samples each
#define PAD   3084             // Wt row stride (mult of 4; 3084 % 32 = 12)
#define SCALE 0.999999f        // 1 - c*ns
#define NSTAB 1e-7f
#define EPS2  0.01f

#define WT_BYTES (NCLS * PAD * 4)   // 123360

__device__ float        g_norm[BATCH];
__device__ unsigned int g_count;     // zero-init; reset in-kernel

// ---------------------------------------------------------------------------
// Warp-autonomous fused kernel:
//   prologue: W -> smem transposed Wt[10][PAD]; in-block G = W^T W.
//   main:     each warp owns task = bid + 148*wid (2 samples); x via LDG.128,
//             W via conflict-free LDS.128 (shared by both samples); epilogue
//             entirely in-warp.  NO __syncthreads in the main loop.
//   tail:     last-arriving block reduces g_norm -> out.
// ---------------------------------------------------------------------------
__global__ void __launch_bounds__(TPB, 1)
k_fused(const float* __restrict__ data,
        const float* __restrict__ W,
        const float* __restrict__ b,
        float* __restrict__ out) {
    extern __shared__ float Wt[];             // [NCLS][PAD]
    __shared__ float Gs[NCLS * NCLS];
    __shared__ float shop[NWARP][56];         // G staging
    __shared__ float scr[NWARP][8][NCLS];     // per-warp logit staging
    __shared__ float shp[NWARP][NCLS];
    __shared__ float sha[NWARP][MDIM];
    __shared__ float shb[NWARP][MDIM];
    __shared__ float shg[NWARP][NCLS];
    __shared__ float red[TPB];
    __shared__ unsigned int s_rank;

    const int tid  = threadIdx.x;
    const int lane = tid & 31;
    const int wid  = tid >> 5;

    // ---- stage 1: W -> Wt (transposed) via coalesced float4 reads + scalar
    // scatter stores.  Element e: d = e/10, l = e%10 tracked incrementally.
    {
        const float4* W4 = (const float4*)W;   // 7680 float4
        int d = (4 * tid) / NCLS;
        int l = (4 * tid) % NCLS;
        for (int i = 0; i < 30; i++) {
            const float4 v = W4[tid + i * TPB];
            int dd = d, ll = l;
            Wt[ll * PAD + dd] = v.x;
            if (++ll == NCLS) { ll = 0; dd++; }
            Wt[ll * PAD + dd] = v.y;
            if (++ll == NCLS) { ll = 0; dd++; }
            Wt[ll * PAD + dd] = v.z;
            if (++ll == NCLS) { ll = 0; dd++; }
            Wt[ll * PAD + dd] = v.w;
            // advance e by 4*TPB = 1024 = 102*10 + 4
            d += 102; l += 4;
            if (l >= NCLS) { l -= NCLS; d++; }
        }
    }
    __syncthreads();

    // ---- stage 2: G = W^T W (upper triangle) from smem rows
    {
        float op[55];
        #pragma unroll
        for (int e = 0; e < 55; e++) op[e] = 0.f;
        #pragma unroll
        for (int i = 0; i < 12; i++) {
            const int d = tid + i * TPB;
            float wrow[NCLS];
            #pragma unroll
            for (int l = 0; l < NCLS; l++) wrow[l] = Wt[l * PAD + d];
            int e = 0;
            #pragma unroll
            for (int i2 = 0; i2 < NCLS; i2++)
                #pragma unroll
                for (int j2 = i2; j2 < NCLS; j2++)
                    op[e++] += wrow[i2] * wrow[j2];
        }
        #pragma unroll
        for (int e = 0; e < 55; e++) {
            #pragma unroll
            for (int off = 16; off; off >>= 1)
                op[e] += __shfl_xor_sync(0xFFFFFFFFu, op[e], off);
        }
        if (lane == 0) {
            #pragma unroll
            for (int e = 0; e < 55; e++) shop[wid][e] = op[e];
        }
    }
    __syncthreads();
    if (tid < 55) {
        float t = 0.f;
        #pragma unroll
        for (int w = 0; w < NWARP; w++) t += shop[w][tid];
        int e = tid, i = 0;
        while (e >= NCLS - i) { e -= NCLS - i; i++; }
        const int j = i + e;
        Gs[i * NCLS + j] = t;
        Gs[j * NCLS + i] = t;
    }
    __syncthreads();

    // ---- main: warp-autonomous, no block barriers
    const int task = blockIdx.x + gridDim.x * wid;
    if (task < NTASK) {
        const float bl = (lane < NCLS) ? b[lane] : 0.f;
        const float4* xp0 =
            (const float4*)(data + (size_t)(2 * task) * DIM) + lane;
        const float4* xp1 = xp0 + DIM / 4;

        float acc0[NCLS], acc1[NCLS];
        #pragma unroll
        for (int l = 0; l < NCLS; l++) { acc0[l] = 0.f; acc1[l] = 0.f; }

        // double-buffered x streaming: 4 chunks of 6 float4 per sample
        float4 b0[2][6], b1[2][6];
        #pragma unroll
        for (int k = 0; k < 6; k++) {
            b0[0][k] = xp0[32 * k];
            b1[0][k] = xp1[32 * k];
        }
        #pragma unroll
        for (int c = 0; c < 4; c++) {
            const int cur = c & 1, nxt = cur ^ 1;
            if (c < 3) {
                #pragma unroll
                for (int k = 0; k < 6; k++) {
                    b0[nxt][k] = xp0[32 * (6 * (c + 1) + k)];
                    b1[nxt][k] = xp1[32 * (6 * (c + 1) + k)];
                }
            }
            #pragma unroll
            for (int k = 0; k < 6; k++) {
                const int d4 = lane + 32 * (6 * c + k);
                const float4 xa = b0[cur][k];
                const float4 xb = b1[cur][k];
                #pragma unroll
                for (int l = 0; l < NCLS; l++) {
                    const float4 w =
                        *(const float4*)(Wt + l * PAD + 4 * d4);
                    acc0[l] += xa.x * w.x + xa.y * w.y
                             + xa.z * w.z + xa.w * w.w;
                    acc1[l] += xb.x * w.x + xb.y * w.y
                             + xb.z * w.z + xb.w * w.w;
                }
            }
        }

        // ---- per-sample in-warp epilogue
        #pragma unroll
        for (int ss = 0; ss < 2; ss++) {
            float a[NCLS];
            #pragma unroll
            for (int l = 0; l < NCLS; l++)
                a[l] = ss ? acc1[l] : acc0[l];
            // 2-step butterfly -> lanes 0..7 hold 4-lane-group sums
            #pragma unroll
            for (int l = 0; l < NCLS; l++) {
                #pragma unroll
                for (int off = 16; off >= 8; off >>= 1)
                    a[l] += __shfl_xor_sync(0xFFFFFFFFu, a[l], off);
            }
            if (lane < 8) {
                #pragma unroll
                for (int l = 0; l < NCLS; l++) scr[wid][lane][l] = a[l];
            }
            __syncwarp();
            float logit = -1e30f;
            if (lane < NCLS) {
                float v = bl;
                #pragma unroll
                for (int g = 0; g < 8; g++) v += scr[wid][g][lane];
                logit = v;
            }
            // softmax over lanes 0..9 (16-lane butterfly; lanes 16..31 get
            // correct scalars via the factor broadcast below)
            float mval = logit;
            #pragma unroll
            for (int off = 8; off; off >>= 1)
                mval = fmaxf(mval, __shfl_xor_sync(0xFFFFFFFFu, mval, off));
            float e = (lane < NCLS) ? expf(logit - mval) : 0.f;
            float ssum = e;
            #pragma unroll
            for (int off = 8; off; off >>= 1)
                ssum += __shfl_xor_sync(0xFFFFFFFFu, ssum, off);
            const float p  = e / ssum;
            const float q  = p * SCALE + NSTAB;
            const float nc = sqrtf(q);
            float ncs = (lane < NCLS) ? nc : 0.f;
            #pragma unroll
            for (int off = 8; off; off >>= 1)
                ncs += __shfl_xor_sync(0xFFFFFFFFu, ncs, off);
            const float nc9 = __shfl_sync(0xFFFFFFFFu, nc, 9);
            const float p9  = __shfl_sync(0xFFFFFFFFu, p, 9);
            const float denom = 1.f - nc9;
            float arg = ncs * 0.3162277660168379f;   // 1/sqrt(10)
            arg = fminf(arg, 1.f);
            const float delta  = 2.f * acosf(arg);
            float factor = delta * delta / (4.f * denom * denom * EPS2);
            factor = __shfl_sync(0xFFFFFFFFu, factor, 0);

            if (lane < NCLS) shp[wid][lane] = p;
            if (lane < MDIM) {
                sha[wid][lane] = SCALE * p / (nc * denom);
                shb[wid][lane] = SCALE * nc * p9 / (nc9 * denom * denom);
            }
            __syncwarp();
            if (lane < NCLS) {
                float gg = 0.f;
                #pragma unroll
                for (int k2 = 0; k2 < NCLS; k2++)
                    gg += Gs[lane * NCLS + k2] * shp[wid][k2];
                shg[wid][lane] = gg;
            }
            __syncwarp();
            float sdot = 0.f;
            #pragma unroll
            for (int k2 = 0; k2 < NCLS; k2++)
                sdot += shp[wid][k2] * shg[wid][k2];
            const float tval = shg[wid][MDIM];
            const float r    = Gs[MDIM * NCLS + MDIM];

            // M = A G A^T via rank structure (81 entries over 32 lanes)
            float ssq = 0.f;
            #pragma unroll
            for (int rep = 0; rep < 3; rep++) {
                const int e2 = lane + rep * 32;
                if (e2 < MDIM * MDIM) {
                    const int i = e2 / MDIM, j = e2 % MDIM;
                    const float ai = sha[wid][i], aj = sha[wid][j];
                    const float bi = shb[wid][i], bj = shb[wid][j];
                    const float gi = -(ai + bi), gj = -(aj + bj);
                    const float ggi = shg[wid][i], ggj = shg[wid][j];
                    float Mij = ai * aj * Gs[i * NCLS + j]
                              + ai * bj * Gs[i * NCLS + MDIM]
                              + bi * aj * Gs[j * NCLS + MDIM]
                              + ai * gj * ggi
                              + gi * aj * ggj
                              + bi * bj * r
                              + (bi * gj + gi * bj) * tval
                              + gi * gj * sdot;
                    const float v2 = Mij - ((i == j) ? factor : 0.f);
                    ssq += v2 * v2;
                }
            }
            #pragma unroll
            for (int off = 16; off; off >>= 1)
                ssq += __shfl_xor_sync(0xFFFFFFFFu, ssq, off);
            if (lane == 0) g_norm[2 * task + ss] = sqrtf(ssq);
            __syncwarp();   // scr/shp reuse safety for next sample
        }
    }

    // ---- fused final reduction: last block to arrive does it
    __syncthreads();
    if (tid == 0) {
        __threadfence();                        // publish g_norm writes
        s_rank = atomicAdd(&g_count, 1u);
    }
    __syncthreads();
    if (s_rank == GRID - 1) {                   // uniform across block
        __threadfence();                        // acquire others' g_norm
        float t0 = 0.f, t1 = 0.f;
        #pragma unroll
        for (int k = 0; k < BATCH / TPB; k += 2) {
            t0 += g_norm[tid + k * TPB];
            t1 += g_norm[tid + (k + 1) * TPB];
        }
        red[tid] = t0 + t1;
        __syncthreads();
        #pragma unroll
        for (int off = TPB / 2; off; off >>= 1) {
            if (tid < off) red[tid] += red[tid + off];
            __syncthreads();
        }
        if (tid == 0) {
            out[0] = red[0] * (1.0f / (BATCH * 81.0f));
            g_count = 0;                        // reset for next graph replay
        }
    }
}

// ---------------------------------------------------------------------------
extern "C" void kernel_launch(void* const* d_in, const int* in_sizes, int n_in,
                              void* d_out, int out_size) {
    // Bind inputs by element count (robust to ordering):
    //   data = 6291456, W = 30720, b = 10.
    const float* data = 0;
    const float* W    = 0;
    const float* b    = 0;
    for (int i = 0; i < n_in; i++) {
        if (in_sizes[i] == BATCH * DIM)      data = (const float*)d_in[i];
        else if (in_sizes[i] == DIM * NCLS)  W    = (const float*)d_in[i];
        else if (in_sizes[i] == NCLS)        b    = (const float*)d_in[i];
    }
    float* out = (float*)d_out;

    cudaFuncSetAttribute(k_fused,
                         cudaFuncAttributeMaxDynamicSharedMemorySize,
                         WT_BYTES);
    k_fused<<<GRID, TPB, WT_BYTES>>>(data, W, b, out);
}